// round 4
// baseline (speedup 1.0000x reference)
#include <cuda_runtime.h>

// FeedForwardNet_72335839199562 — NEAT feed-forward DAG scan, fused kernel.
// B=4096 batch rows, N=2048 nodes (first 512 are inputs), 1536 evaluated nodes.
// Each CTA owns TB=16 batch rows; activations live in 128KB shared memory.
// Each warp privately owns 2 batch rows (no cross-warp data deps). Nodes are
// processed in groups of G=8: the dense part over already-final columns is a
// register-blocked dot (float4 LDS for act, coalesced float4 LDG for W; all 8
// warps walk the same W rows in lockstep so W is L1-served after one L2 fetch
// per CTA), butterfly-reduced across lanes; the strictly-triangular in-group
// tail (<=28 scalar FMAs) is evaluated redundantly on all lanes (all lanes
// hold identical reduced sums -> deterministic). The per-group __syncthreads
// is a locality lockstep for W reuse, not a correctness barrier.

#define B_TOTAL 4096
#define N_IN    512
#define N_NODES 2048
#define N_EVAL  1536
#define N_OUT   256
#define TB      16      // batch rows per CTA
#define G       8       // nodes per group
#define THREADS 256     // 8 warps: warp w owns rows 2w, 2w+1

__device__ __forceinline__ float sigmoid5(float z) {
    float t = fminf(fmaxf(5.0f * z, -60.0f), 60.0f);
    return 1.0f / (1.0f + __expf(-t));
}

__global__ __launch_bounds__(THREADS, 1)
void neat_scan_kernel(const float* __restrict__ x,
                      const float* __restrict__ W,
                      const float* __restrict__ b,
                      float* __restrict__ out)
{
    extern __shared__ float sAct[];   // [TB][N_NODES]
    const int tid  = threadIdx.x;
    const int warp = tid >> 5;
    const int lane = tid & 31;
    const int rowBase = blockIdx.x * TB;

    // ---- init: load x rows, zero the rest -------------------------------
    {
        const float4* xblk = (const float4*)(x + (size_t)rowBase * N_IN);
        const int XQ = N_IN / 4;                  // 128 float4 per row
        for (int e = tid; e < TB * XQ; e += THREADS) {
            int r = e / XQ, c = e % XQ;
            ((float4*)(sAct + r * N_NODES))[c] = xblk[(size_t)r * XQ + c];
        }
        const int ZQ = (N_NODES - N_IN) / 4;      // 384 float4 per row
        const float4 z4 = make_float4(0.f, 0.f, 0.f, 0.f);
        for (int e = tid; e < TB * ZQ; e += THREADS) {
            int r = e / ZQ, c = e % ZQ;
            ((float4*)(sAct + r * N_NODES + N_IN))[c] = z4;
        }
    }
    __syncthreads();

    float* a0row = sAct + (warp * 2 + 0) * N_NODES;
    float* a1row = sAct + (warp * 2 + 1) * N_NODES;

    // ---- sequential scan over node groups -------------------------------
    for (int ib = 0; ib < N_EVAL; ib += G) {
        const int L = N_IN + ib;                 // columns that are final
        float acc0[G], acc1[G];
        #pragma unroll
        for (int g = 0; g < G; ++g) { acc0[g] = 0.f; acc1[g] = 0.f; }

        const float* Wg = W + (size_t)ib * N_NODES;

        // hoist biases (broadcast load, L1-hot)
        float bg[G];
        #pragma unroll
        for (int g = 0; g < G; ++g) bg[g] = b[ib + g];

        // dense part: acc[g] += W[ib+g][j] * act[r][j], j < L
        for (int j = lane * 4; j < L; j += 128) {
            const float4 a0 = *(const float4*)(a0row + j);
            const float4 a1 = *(const float4*)(a1row + j);
            #pragma unroll
            for (int g = 0; g < G; ++g) {
                const float4 wv = *(const float4*)(Wg + (size_t)g * N_NODES + j);
                acc0[g] = fmaf(wv.x, a0.x, acc0[g]);
                acc0[g] = fmaf(wv.y, a0.y, acc0[g]);
                acc0[g] = fmaf(wv.z, a0.z, acc0[g]);
                acc0[g] = fmaf(wv.w, a0.w, acc0[g]);
                acc1[g] = fmaf(wv.x, a1.x, acc1[g]);
                acc1[g] = fmaf(wv.y, a1.y, acc1[g]);
                acc1[g] = fmaf(wv.z, a1.z, acc1[g]);
                acc1[g] = fmaf(wv.w, a1.w, acc1[g]);
            }
        }

        // butterfly reduce across 32 lanes — every lane ends with full sums
        #pragma unroll
        for (int g = 0; g < G; ++g) {
            #pragma unroll
            for (int s = 16; s > 0; s >>= 1) {
                acc0[g] += __shfl_xor_sync(0xffffffffu, acc0[g], s);
                acc1[g] += __shfl_xor_sync(0xffffffffu, acc1[g], s);
            }
            acc0[g] += bg[g];
            acc1[g] += bg[g];
        }

        // strictly-triangular in-group tail (redundant on all lanes)
        #pragma unroll
        for (int g = 0; g < G; ++g) {
            const float o0 = sigmoid5(acc0[g]);
            const float o1 = sigmoid5(acc1[g]);
            const int col = N_IN + ib + g;
            #pragma unroll
            for (int g2 = g + 1; g2 < G; ++g2) {
                const float wt = Wg[(size_t)g2 * N_NODES + col];
                acc0[g2] = fmaf(wt, o0, acc0[g2]);
                acc1[g2] = fmaf(wt, o1, acc1[g2]);
            }
            if (lane == 0) {
                a0row[col] = o0;
                a1row[col] = o1;
            }
        }
        __syncthreads();   // locality lockstep: keep all warps on same W rows
    }

    // ---- write output: last N_OUT node columns --------------------------
    const int OUT_BASE = N_NODES - N_OUT;  // 1792
    for (int e = tid; e < TB * N_OUT; e += THREADS) {
        int r = e / N_OUT, c = e % N_OUT;
        out[(size_t)(rowBase + r) * N_OUT + c] = sAct[r * N_NODES + OUT_BASE + c];
    }
}

extern "C" void kernel_launch(void* const* d_in, const int* in_sizes, int n_in,
                              void* d_out, int out_size)
{
    const float* x = (const float*)d_in[0];   // [4096, 512]
    const float* W = (const float*)d_in[1];   // [1536, 2048]
    const float* b = (const float*)d_in[2];   // [1536]
    float* out = (float*)d_out;               // [4096, 256]

    const size_t smem = (size_t)TB * N_NODES * sizeof(float);  // 128 KB
    cudaFuncSetAttribute(neat_scan_kernel,
                         cudaFuncAttributeMaxDynamicSharedMemorySize, (int)smem);
    neat_scan_kernel<<<B_TOTAL / TB, THREADS, smem>>>(x, W, b, out);
}

// round 6
// speedup vs baseline: 1.4208x; 1.4208x over previous
#include <cuda_runtime.h>
#include <cstdint>

// FeedForwardNet_72335839199562 — NEAT feed-forward DAG scan, v2.
// B=4096, N=2048 nodes (512 inputs), 1536 evaluated. TB=32 rows/CTA ->
// 128 CTAs (one wave). 512 threads = 16 warps; warp w privately owns rows
// 2w, 2w+1. Evaluated activations (cols 512..2047) live in 192KB smem;
// the static input part (cols 0..511) is re-read from global (L2-resident).
// Dense work uses packed fma.rn.f32x2 on adjacent column pairs (both W and
// act pairs are adjacent in the 16B vector loads -> no packing ops).
// Nodes go in groups of G=12: dense partial dots -> butterfly reduce ->
// serial in-group triangular tail computed redundantly on all lanes, with
// the 12x12 in-group W block staged in double-buffered smem.

#define N_IN    512
#define N_NODES 2048
#define N_EVAL  1536
#define N_OUT   256
#define TB      32
#define G       12
#define NGROUPS (N_EVAL / G)     // 128
#define THREADS 512

typedef unsigned long long ull;

__device__ __forceinline__ float sigmoid5(float z) {
    float t = fminf(fmaxf(5.0f * z, -60.0f), 60.0f);
    return 1.0f / (1.0f + __expf(-t));
}

// packed dual-FMA: d.lo = a.lo*b.lo + c.lo ; d.hi = a.hi*b.hi + c.hi
__device__ __forceinline__ ull ffma2(ull a, ull b, ull c) {
    ull d;
    asm("fma.rn.f32x2 %0, %1, %2, %3;" : "=l"(d) : "l"(a), "l"(b), "l"(c));
    return d;
}

__device__ __forceinline__ float lo32(ull v) { return __uint_as_float((unsigned)v); }
__device__ __forceinline__ float hi32(ull v) { return __uint_as_float((unsigned)(v >> 32)); }

__global__ __launch_bounds__(THREADS, 1)
void neat_scan_kernel(const float* __restrict__ x,
                      const float* __restrict__ W,
                      const float* __restrict__ b,
                      float* __restrict__ out)
{
    extern __shared__ float smem[];
    float* sEval = smem;                                    // [TB][N_EVAL]
    float* sWblk = smem + TB * N_EVAL;                      // [2][G][G+1]

    const int tid  = threadIdx.x;
    const int warp = tid >> 5;
    const int lane = tid & 31;
    const int rowBase = blockIdx.x * TB;

    // ---- init: zero evaluated-activation store ---------------------------
    {
        float4* p = (float4*)sEval;
        const int nq = TB * N_EVAL / 4;                     // 12288
        const float4 z4 = make_float4(0.f, 0.f, 0.f, 0.f);
        for (int e = tid; e < nq; e += THREADS) p[e] = z4;
    }
    // prefetch in-group W block for group 0 (parity 0)
    if (tid < G * G) {
        int r = tid / G, c = tid % G;
        sWblk[r * (G + 1) + c] = W[(size_t)r * N_NODES + (N_IN + c)];
    }
    __syncthreads();

    const float* x0 = x + (size_t)(rowBase + warp * 2 + 0) * N_IN;
    const float* x1 = x + (size_t)(rowBase + warp * 2 + 1) * N_IN;
    float* ev0 = sEval + (warp * 2 + 0) * N_EVAL;
    float* ev1 = sEval + (warp * 2 + 1) * N_EVAL;

    // ---- sequential scan over node groups -------------------------------
    for (int grp = 0; grp < NGROUPS; ++grp) {
        const int ib = grp * G;                    // first eval-node of group
        const float* Wg = W + (size_t)ib * N_NODES;

        ull acc0[G], acc1[G];
        #pragma unroll
        for (int g = 0; g < G; ++g) { acc0[g] = 0ull; acc1[g] = 0ull; }

        // --- part A: input columns 0..511 (act from global x) ------------
        #pragma unroll
        for (int it = 0; it < N_IN / 128; ++it) {
            const int j = lane * 4 + it * 128;
            const ulonglong2 a0 = *(const ulonglong2*)(x0 + j);
            const ulonglong2 a1 = *(const ulonglong2*)(x1 + j);
            #pragma unroll
            for (int g = 0; g < G; ++g) {
                const ulonglong2 wv = *(const ulonglong2*)(Wg + (size_t)g * N_NODES + j);
                acc0[g] = ffma2(wv.x, a0.x, acc0[g]);
                acc0[g] = ffma2(wv.y, a0.y, acc0[g]);
                acc1[g] = ffma2(wv.x, a1.x, acc1[g]);
                acc1[g] = ffma2(wv.y, a1.y, acc1[g]);
            }
        }

        // --- part B: evaluated columns 0..ib-1 (act from smem) -----------
        // loop bound rounded up to 128: the extra columns hold zero
        // activations (not yet written), contributing exactly 0.
        const int nB = (ib + 127) & ~127;
        for (int j = lane * 4; j < nB; j += 128) {
            const ulonglong2 a0 = *(const ulonglong2*)(ev0 + j);
            const ulonglong2 a1 = *(const ulonglong2*)(ev1 + j);
            #pragma unroll
            for (int g = 0; g < G; ++g) {
                const ulonglong2 wv = *(const ulonglong2*)(Wg + (size_t)g * N_NODES + N_IN + j);
                acc0[g] = ffma2(wv.x, a0.x, acc0[g]);
                acc0[g] = ffma2(wv.y, a0.y, acc0[g]);
                acc1[g] = ffma2(wv.x, a1.x, acc1[g]);
                acc1[g] = ffma2(wv.y, a1.y, acc1[g]);
            }
        }

        // --- fold packed halves, butterfly reduce, add bias --------------
        float s0[G], s1[G];
        #pragma unroll
        for (int g = 0; g < G; ++g) {
            s0[g] = lo32(acc0[g]) + hi32(acc0[g]);
            s1[g] = lo32(acc1[g]) + hi32(acc1[g]);
            #pragma unroll
            for (int s = 16; s > 0; s >>= 1) {
                s0[g] += __shfl_xor_sync(0xffffffffu, s0[g], s);
                s1[g] += __shfl_xor_sync(0xffffffffu, s1[g], s);
            }
            const float bg = b[ib + g];
            s0[g] += bg;
            s1[g] += bg;
        }

        // --- serial in-group triangular tail (redundant on all lanes) ----
        const float* blk = sWblk + (grp & 1) * G * (G + 1);
        #pragma unroll
        for (int g = 0; g < G; ++g) {
            const float o0 = sigmoid5(s0[g]);
            const float o1 = sigmoid5(s1[g]);
            #pragma unroll
            for (int g2 = g + 1; g2 < G; ++g2) {
                const float wt = blk[g2 * (G + 1) + g];
                s0[g2] = fmaf(wt, o0, s0[g2]);
                s1[g2] = fmaf(wt, o1, s1[g2]);
            }
            if (lane == 0) {
                ev0[ib + g] = o0;
                ev1[ib + g] = o1;
            }
        }

        // --- prefetch next group's in-group W block (other parity) -------
        const int ibn = ib + G;
        if (ibn < N_EVAL && tid < G * G) {
            int r = tid / G, c = tid % G;
            sWblk[((grp + 1) & 1) * G * (G + 1) + r * (G + 1) + c] =
                W[(size_t)(ibn + r) * N_NODES + (N_IN + ibn + c)];
        }
        __syncthreads();   // publishes sWblk; also keeps warps W-lockstepped
    }

    // ---- write output: last N_OUT evaluated columns ---------------------
    const int OUT_BASE = N_EVAL - N_OUT;   // 1280
    for (int e = tid; e < TB * N_OUT; e += THREADS) {
        int r = e / N_OUT, c = e % N_OUT;
        out[(size_t)(rowBase + r) * N_OUT + c] = sEval[r * N_EVAL + OUT_BASE + c];
    }
}

extern "C" void kernel_launch(void* const* d_in, const int* in_sizes, int n_in,
                              void* d_out, int out_size)
{
    const float* x = (const float*)d_in[0];   // [4096, 512]
    const float* W = (const float*)d_in[1];   // [1536, 2048]
    const float* b = (const float*)d_in[2];   // [1536]
    float* out = (float*)d_out;               // [4096, 256]

    const size_t smem = (size_t)TB * N_EVAL * sizeof(float)
                      + 2 * G * (G + 1) * sizeof(float);    // ~193.2 KB
    cudaFuncSetAttribute(neat_scan_kernel,
                         cudaFuncAttributeMaxDynamicSharedMemorySize, (int)smem);
    neat_scan_kernel<<<4096 / TB, THREADS, smem>>>(x, W, b, out);
}

// round 11
// speedup vs baseline: 1.4451x; 1.0171x over previous
#include <cuda_runtime.h>
#include <cstdint>

// FeedForwardNet_72335839199562 — NEAT feed-forward DAG scan, v3.
// Key change vs v2: activations live in a 32MB __device__ scratch (L2), read
// via __ldcg (L1-bypass); smem shrinks to ~1.3KB so L1D is ~220KB and the
// per-group W tile (<=98KB, 16-way warp reuse) is L1-resident. W first-touch
// L2 latency is hidden by warp-0 prefetch.global.L1 one chunk ahead. Acts are
// software-pipelined one chunk ahead in registers.
// 128 CTAs x 512 threads; warp w privately owns batch rows 2w, 2w+1
// (no cross-warp data deps; the per-group barrier publishes the staged
// in-group W block and keeps warps on the same L1-resident W tile).

#define N_IN    512
#define N_NODES 2048
#define N_EVAL  1536
#define N_OUT   256
#define TB      32
#define G       12
#define NGROUPS (N_EVAL / G)     // 128
#define THREADS 512

typedef unsigned long long ull;

__device__ float g_acts[4096 * 2048];   // [B][N_NODES] fp32 scratch (32 MB)

__device__ __forceinline__ float sigmoid5(float z) {
    float t = fminf(fmaxf(5.0f * z, -60.0f), 60.0f);
    return 1.0f / (1.0f + __expf(-t));
}

// packed dual-FMA: d.lo = a.lo*b.lo + c.lo ; d.hi = a.hi*b.hi + c.hi
__device__ __forceinline__ ull ffma2(ull a, ull b, ull c) {
    ull d;
    asm("fma.rn.f32x2 %0, %1, %2, %3;" : "=l"(d) : "l"(a), "l"(b), "l"(c));
    return d;
}
__device__ __forceinline__ float lo32(ull v) { return __uint_as_float((unsigned)v); }
__device__ __forceinline__ float hi32(ull v) { return __uint_as_float((unsigned)(v >> 32)); }
__device__ __forceinline__ ull d2u_lo(double2 d) { return (ull)__double_as_longlong(d.x); }
__device__ __forceinline__ ull d2u_hi(double2 d) { return (ull)__double_as_longlong(d.y); }

__device__ __forceinline__ void l1_prefetch(const float* p) {
    asm volatile("prefetch.global.L1 [%0];" :: "l"(p));
}

__global__ __launch_bounds__(THREADS, 1)
void neat_scan_kernel(const float* __restrict__ x,
                      const float* __restrict__ W,
                      const float* __restrict__ b,
                      float* __restrict__ out)
{
    __shared__ float sWblk[2][G][G + 1];   // double-buffered in-group W block

    const int tid  = threadIdx.x;
    const int warp = tid >> 5;
    const int lane = tid & 31;
    const int rowBase = blockIdx.x * TB;

    float* actBase = g_acts + (size_t)rowBase * N_NODES;

    // ---- init acts slab: copy x into cols [0,512), zero cols [512,2048) ----
    {
        const int XQ = N_IN / 4;                  // 128 float4 per row
        for (int e = tid; e < TB * XQ; e += THREADS) {
            int r = e >> 7, c = e & 127;
            ((float4*)(actBase + (size_t)r * N_NODES))[c] =
                ((const float4*)(x + (size_t)(rowBase + r) * N_IN))[c];
        }
        const int ZQ = (N_NODES - N_IN) / 4;      // 384 float4 per row
        const float4 z4 = make_float4(0.f, 0.f, 0.f, 0.f);
        for (int e = tid; e < TB * ZQ; e += THREADS) {
            int r = e / ZQ, c = e % ZQ;
            ((float4*)(actBase + (size_t)r * N_NODES + N_IN))[c] = z4;
        }
    }
    // stage in-group W block for group 0 into parity 0
    if (tid < G * G) {
        int r = tid / G, c = tid % G;
        sWblk[0][r][c] = W[(size_t)r * N_NODES + (N_IN + c)];
    }
    // prefetch group 0 / chunk 0 of W into L1
    if (warp == 0) {
        #pragma unroll
        for (int i = 0; i < 2; ++i) {
            int idx = lane + 32 * i;               // 48 lines: 12 rows x 4 lines
            if (idx < 48)
                l1_prefetch(W + (size_t)(idx >> 2) * N_NODES + (idx & 3) * 32);
        }
    }
    __syncthreads();

    float* a0 = actBase + (size_t)(warp * 2 + 0) * N_NODES;
    float* a1 = actBase + (size_t)(warp * 2 + 1) * N_NODES;

    // ---- sequential scan over node groups -------------------------------
    for (int grp = 0; grp < NGROUPS; ++grp) {
        const int ib = grp * G;
        const float* Wg = W + (size_t)ib * N_NODES;
        // cols [0, nL): over-read past L=512+ib hits zero-initialized acts
        const int nL = N_IN + ((ib + 127) & ~127);

        ull acc0[G], acc1[G];
        #pragma unroll
        for (int g = 0; g < G; ++g) { acc0[g] = 0ull; acc1[g] = 0ull; }

        // act pipeline: preload chunk 0
        double2 av0 = __ldcg((const double2*)(a0 + lane * 4));
        double2 av1 = __ldcg((const double2*)(a1 + lane * 4));

        #pragma unroll 1
        for (int base = 0; base < nL; base += 128) {
            const int nbase = base + 128;
            // prefetch next chunk's acts into registers
            double2 nv0 = av0, nv1 = av1;
            if (nbase < nL) {
                nv0 = __ldcg((const double2*)(a0 + nbase + lane * 4));
                nv1 = __ldcg((const double2*)(a1 + nbase + lane * 4));
            }
            // warp 0: prefetch next chunk's W lines into L1 (48 lines)
            if (warp == 0 && nbase < nL) {
                #pragma unroll
                for (int i = 0; i < 2; ++i) {
                    int idx = lane + 32 * i;
                    if (idx < 48)
                        l1_prefetch(Wg + (size_t)(idx >> 2) * N_NODES + nbase + (idx & 3) * 32);
                }
            }
            const int col = base + lane * 4;
            const ull a0lo = d2u_lo(av0), a0hi = d2u_hi(av0);
            const ull a1lo = d2u_lo(av1), a1hi = d2u_hi(av1);
            #pragma unroll
            for (int g = 0; g < G; ++g) {
                const ulonglong2 wv = *(const ulonglong2*)(Wg + (size_t)g * N_NODES + col);
                acc0[g] = ffma2(wv.x, a0lo, acc0[g]);
                acc0[g] = ffma2(wv.y, a0hi, acc0[g]);
                acc1[g] = ffma2(wv.x, a1lo, acc1[g]);
                acc1[g] = ffma2(wv.y, a1hi, acc1[g]);
            }
            av0 = nv0; av1 = nv1;
        }

        // --- fold packed halves, butterfly reduce, add bias --------------
        float s0[G], s1[G];
        #pragma unroll
        for (int g = 0; g < G; ++g) {
            s0[g] = lo32(acc0[g]) + hi32(acc0[g]);
            s1[g] = lo32(acc1[g]) + hi32(acc1[g]);
            #pragma unroll
            for (int s = 16; s > 0; s >>= 1) {
                s0[g] += __shfl_xor_sync(0xffffffffu, s0[g], s);
                s1[g] += __shfl_xor_sync(0xffffffffu, s1[g], s);
            }
            const float bg = b[ib + g];
            s0[g] += bg;
            s1[g] += bg;
        }

        // --- serial in-group triangular tail (redundant on all lanes) ----
        const float* blk = &sWblk[grp & 1][0][0];
        #pragma unroll
        for (int g = 0; g < G; ++g) {
            const float o0 = sigmoid5(s0[g]);
            const float o1 = sigmoid5(s1[g]);
            #pragma unroll
            for (int g2 = g + 1; g2 < G; ++g2) {
                const float wt = blk[g2 * (G + 1) + g];
                s0[g2] = fmaf(wt, o0, s0[g2]);
                s1[g2] = fmaf(wt, o1, s1[g2]);
            }
            if (lane == 0) {
                a0[N_IN + ib + g] = o0;     // STG -> L2; read back via __ldcg
                a1[N_IN + ib + g] = o1;
            }
        }

        // --- prep next group: stage W block + prefetch its chunk 0 -------
        const int ibn = ib + G;
        if (ibn < N_EVAL) {
            if (tid < G * G) {
                int r = tid / G, c = tid % G;
                sWblk[(grp + 1) & 1][r][c] =
                    W[(size_t)(ibn + r) * N_NODES + (N_IN + ibn + c)];
            }
            if (warp == 0) {
                const float* Wn = W + (size_t)ibn * N_NODES;
                #pragma unroll
                for (int i = 0; i < 2; ++i) {
                    int idx = lane + 32 * i;
                    if (idx < 48)
                        l1_prefetch(Wn + (size_t)(idx >> 2) * N_NODES + (idx & 3) * 32);
                }
            }
        }
        __syncthreads();   // publish sWblk; keep warps on same L1 W tile
    }

    // ---- write output: node cols [1792, 2048) ---------------------------
    const int OUT_BASE = N_NODES - N_OUT;   // 1792
    for (int e = tid; e < TB * N_OUT; e += THREADS) {
        int r = e / N_OUT, c = e % N_OUT;
        out[(size_t)(rowBase + r) * N_OUT + c] =
            actBase[(size_t)r * N_NODES + OUT_BASE + c];
    }
}

extern "C" void kernel_launch(void* const* d_in, const int* in_sizes, int n_in,
                              void* d_out, int out_size)
{
    const float* x = (const float*)d_in[0];   // [4096, 512]
    const float* W = (const float*)d_in[1];   // [1536, 2048]
    const float* b = (const float*)d_in[2];   // [1536]
    float* out = (float*)d_out;               // [4096, 256]

    neat_scan_kernel<<<4096 / TB, THREADS>>>(x, W, b, out);
}